// round 1
// baseline (speedup 1.0000x reference)
#include <cuda_runtime.h>
#include <math.h>

#define NH   16
#define NKV  8
#define D    128
#define HID  2048
#define QKV_N ((NH + 2 * NKV) * D)   /* 4096 */
#define MAXT 2048

/* ---------------- scratch (no allocations allowed) ---------------- */
__device__ float g_qkv[(size_t)MAXT * QKV_N];       /* 32 MB */
__device__ float g_q  [(size_t)MAXT * NH  * D];     /* 16 MB */
__device__ float g_k  [(size_t)MAXT * NKV * D];     /*  8 MB */
__device__ float g_attn[(size_t)MAXT * NH * D];     /* 16 MB */

/* ---------------- tiled fp32 GEMM: C[M,N] = A[M,K] @ B[K,N] -------- */
#define BM 64
#define BN 64
#define BK 16

__device__ __forceinline__ void sgemm_body(const float* __restrict__ A,
                                           const float* __restrict__ B,
                                           float* __restrict__ C,
                                           int M, int N, int K)
{
    __shared__ __align__(16) float As[BK][BM + 4];
    __shared__ __align__(16) float Bs[BK][BN + 4];

    const int tid = threadIdx.x;
    const int tx  = tid & 15;
    const int ty  = tid >> 4;
    const int m0  = blockIdx.y * BM;
    const int n0  = blockIdx.x * BN;

    float acc[4][4];
#pragma unroll
    for (int i = 0; i < 4; i++)
#pragma unroll
        for (int j = 0; j < 4; j++) acc[i][j] = 0.f;

    const int ar = tid >> 2;          /* 0..63 */
    const int ac = (tid & 3) << 2;    /* 0,4,8,12 */
    const int br = tid >> 4;          /* 0..15 */
    const int bc = (tid & 15) << 2;   /* 0..60 */

    for (int k0 = 0; k0 < K; k0 += BK) {
        float4 a4 = *(const float4*)&A[(size_t)(m0 + ar) * K + k0 + ac];
        As[ac + 0][ar] = a4.x;
        As[ac + 1][ar] = a4.y;
        As[ac + 2][ar] = a4.z;
        As[ac + 3][ar] = a4.w;
        *(float4*)&Bs[br][bc] = *(const float4*)&B[(size_t)(k0 + br) * N + n0 + bc];
        __syncthreads();

#pragma unroll
        for (int k = 0; k < BK; k++) {
            float4 av = *(const float4*)&As[k][ty * 4];
            float4 bv = *(const float4*)&Bs[k][tx * 4];
            acc[0][0] += av.x * bv.x; acc[0][1] += av.x * bv.y;
            acc[0][2] += av.x * bv.z; acc[0][3] += av.x * bv.w;
            acc[1][0] += av.y * bv.x; acc[1][1] += av.y * bv.y;
            acc[1][2] += av.y * bv.z; acc[1][3] += av.y * bv.w;
            acc[2][0] += av.z * bv.x; acc[2][1] += av.z * bv.y;
            acc[2][2] += av.z * bv.z; acc[2][3] += av.z * bv.w;
            acc[3][0] += av.w * bv.x; acc[3][1] += av.w * bv.y;
            acc[3][2] += av.w * bv.z; acc[3][3] += av.w * bv.w;
        }
        __syncthreads();
    }

#pragma unroll
    for (int i = 0; i < 4; i++) {
        float4 r = make_float4(acc[i][0], acc[i][1], acc[i][2], acc[i][3]);
        *(float4*)&C[(size_t)(m0 + ty * 4 + i) * N + n0 + tx * 4] = r;
    }
}

__global__ __launch_bounds__(256) void qkv_gemm(const float* __restrict__ A,
                                                const float* __restrict__ B,
                                                int T)
{
    sgemm_body(A, B, g_qkv, T, QKV_N, HID);
}

__global__ __launch_bounds__(256) void out_gemm(const float* __restrict__ B,
                                                float* __restrict__ C,
                                                int T)
{
    sgemm_body(g_attn, B, C, T, HID, HID);
}

/* ---------------- RMSNorm + RoPE for q and k ----------------------- */
__global__ __launch_bounds__(128) void normrope_kernel(const int* __restrict__ positions,
                                                       const float* __restrict__ q_norm_w,
                                                       const float* __restrict__ k_norm_w,
                                                       int T)
{
    const int t = blockIdx.x;
    const int h = blockIdx.y;            /* 0..NH-1 => q head, else kv head */
    const int d = threadIdx.x;           /* 0..127 */

    const float* src;
    const float* w;
    float* dst;
    if (h < NH) {
        src = g_qkv + (size_t)t * QKV_N + h * D;
        w   = q_norm_w;
        dst = g_q + ((size_t)t * NH + h) * D;
    } else {
        int hk = h - NH;
        src = g_qkv + (size_t)t * QKV_N + NH * D + hk * D;
        w   = k_norm_w;
        dst = g_k + ((size_t)t * NKV + hk) * D;
    }

    float x = src[d];
    float ss = x * x;
#pragma unroll
    for (int o = 16; o > 0; o >>= 1) ss += __shfl_xor_sync(0xFFFFFFFFu, ss, o);

    __shared__ float red[4];
    __shared__ float s[D];
    if ((d & 31) == 0) red[d >> 5] = ss;
    __syncthreads();
    float var = (red[0] + red[1] + red[2] + red[3]) * (1.0f / (float)D);
    float nx = x * rsqrtf(var + 1e-6f) * w[d];
    s[d] = nx;
    __syncthreads();

    if (d < D / 2) {
        float p = (float)positions[t];
        float inv = (float)(1.0 / pow(1000000.0, (double)d / (double)(D / 2)));
        float ang = p * inv;
        float c = cosf(ang);
        float si = sinf(ang);
        float x1 = s[d];
        float x2 = s[d + D / 2];
        dst[d]         = x1 * c - x2 * si;
        dst[d + D / 2] = x2 * c + x1 * si;
    }
}

/* ---------------- causal flash attention (fp32) --------------------- */
#define AT_BM 128
#define AT_BN 32
#define QS_LD 132   /* row stride (floats): conflict-free LDS.128 phases */

extern __shared__ float s_attn[];

__global__ __launch_bounds__(128) void attn_kernel(int T)
{
    float* qs = s_attn;                       /* 128 x 132 */
    float* ks = qs + AT_BM * QS_LD;           /*  32 x 132 */
    float* vs = ks + AT_BN * QS_LD;           /*  32 x 132 */

    const int h   = blockIdx.y;
    const int hk  = h >> 1;                   /* group = NH/NKV = 2 */
    const int m0  = blockIdx.x * AT_BM;
    const int tid = threadIdx.x;
    const float scale = 0.08838834764831845f; /* 1/sqrt(128) */

    /* load + pre-scale q tile (coalesced: 32 float4 lanes per row) */
    {
        const int c = tid & 31;
        const int r = tid >> 5;
#pragma unroll
        for (int p = 0; p < AT_BM / 4; p++) {
            int row = r + p * 4;
            float4 v = *(const float4*)&g_q[((size_t)(m0 + row) * NH + h) * D + c * 4];
            v.x *= scale; v.y *= scale; v.z *= scale; v.w *= scale;
            *(float4*)&qs[row * QS_LD + c * 4] = v;
        }
    }

    float4 acc[32];
#pragma unroll
    for (int u = 0; u < 32; u++) acc[u] = make_float4(0.f, 0.f, 0.f, 0.f);
    float mrow = -1e30f;
    float lrow = 0.f;
    const int qi = m0 + tid;

    const int ntiles = (m0 + AT_BM) / AT_BN;
    for (int kt = 0; kt < ntiles; kt++) {
        const int k0 = kt * AT_BN;
        __syncthreads();   /* previous tile's smem fully consumed */
        {
            const int c = tid & 31;
            const int r = tid >> 5;
#pragma unroll
            for (int p = 0; p < AT_BN / 4; p++) {
                int row = r + p * 4;
                *(float4*)&ks[row * QS_LD + c * 4] =
                    *(const float4*)&g_k[((size_t)(k0 + row) * NKV + hk) * D + c * 4];
                *(float4*)&vs[row * QS_LD + c * 4] =
                    *(const float4*)&g_qkv[(size_t)(k0 + row) * QKV_N + (NH + NKV) * D + hk * D + c * 4];
            }
        }
        __syncthreads();

        /* scores: s[jj] = q_row . k_jj  (q in regs per 32-dim chunk, k broadcast) */
        float s[AT_BN];
#pragma unroll
        for (int jj = 0; jj < AT_BN; jj++) s[jj] = 0.f;
#pragma unroll
        for (int d0 = 0; d0 < D; d0 += 32) {
            float q[32];
#pragma unroll
            for (int u = 0; u < 8; u++) {
                float4 t4 = *(const float4*)&qs[tid * QS_LD + d0 + u * 4];
                q[u * 4 + 0] = t4.x; q[u * 4 + 1] = t4.y;
                q[u * 4 + 2] = t4.z; q[u * 4 + 3] = t4.w;
            }
            for (int jj = 0; jj < AT_BN; jj++) {
                float sj = 0.f;
#pragma unroll
                for (int u = 0; u < 8; u++) {
                    float4 k4 = *(const float4*)&ks[jj * QS_LD + d0 + u * 4];
                    sj += q[u * 4 + 0] * k4.x + q[u * 4 + 1] * k4.y
                        + q[u * 4 + 2] * k4.z + q[u * 4 + 3] * k4.w;
                }
                s[jj] += sj;
            }
        }

        /* causal mask + online softmax */
        float mt = mrow;
#pragma unroll
        for (int jj = 0; jj < AT_BN; jj++) {
            if (k0 + jj > qi) s[jj] = -1e30f;
            mt = fmaxf(mt, s[jj]);
        }
        float corr = __expf(mrow - mt);
        mrow = mt;
        float psum = 0.f;
#pragma unroll
        for (int jj = 0; jj < AT_BN; jj++) {
            float pj = __expf(s[jj] - mt);
            s[jj] = pj;
            psum += pj;
        }
        lrow = lrow * corr + psum;

#pragma unroll
        for (int u = 0; u < 32; u++) {
            acc[u].x *= corr; acc[u].y *= corr;
            acc[u].z *= corr; acc[u].w *= corr;
        }
        for (int jj = 0; jj < AT_BN; jj++) {
            float pj = s[jj];
#pragma unroll
            for (int u = 0; u < 32; u++) {
                float4 v4 = *(const float4*)&vs[jj * QS_LD + u * 4];
                acc[u].x += pj * v4.x; acc[u].y += pj * v4.y;
                acc[u].z += pj * v4.z; acc[u].w += pj * v4.w;
            }
        }
    }

    const float inv = 1.f / lrow;
#pragma unroll
    for (int u = 0; u < 32; u++) {
        float4 r = acc[u];
        r.x *= inv; r.y *= inv; r.z *= inv; r.w *= inv;
        *(float4*)&g_attn[(size_t)qi * (NH * D) + h * D + u * 4] = r;
    }
}

/* ---------------- launch -------------------------------------------- */
extern "C" void kernel_launch(void* const* d_in, const int* in_sizes, int n_in,
                              void* d_out, int out_size)
{
    const int*   positions = (const int*)d_in[0];
    const float* hidden    = (const float*)d_in[1];
    const float* w_qkv     = (const float*)d_in[2];
    const float* q_norm_w  = (const float*)d_in[3];
    const float* k_norm_w  = (const float*)d_in[4];
    const float* w_o       = (const float*)d_in[5];
    float*       out       = (float*)d_out;
    const int    T         = in_sizes[0];   /* 2048 */

    /* 1) QKV projection: [T,HID] @ [HID,4096] */
    dim3 g1(QKV_N / BN, T / BM);
    qkv_gemm<<<g1, 256>>>(hidden, w_qkv, T);

    /* 2) RMSNorm + RoPE for q and k */
    dim3 g2(T, NH + NKV);
    normrope_kernel<<<g2, 128>>>(positions, q_norm_w, k_norm_w, T);

    /* 3) causal GQA flash attention */
    int smem = (AT_BM + 2 * AT_BN) * QS_LD * (int)sizeof(float);
    cudaFuncSetAttribute(attn_kernel, cudaFuncAttributeMaxDynamicSharedMemorySize, smem);
    dim3 g3(T / AT_BM, NH);
    attn_kernel<<<g3, 128, smem>>>(T);

    /* 4) output projection: [T,2048] @ [2048,2048] */
    dim3 g4(HID / BN, T / BM);
    out_gemm<<<g4, 256>>>(w_o, out, T);
}